// round 6
// baseline (speedup 1.0000x reference)
#include <cuda_runtime.h>

#define BB 64
#define TT 577
#define DD 768
#define DENS 519      // int(577*0.9)
#define NSKIP 58      // 577 - 519
#define D4 (DD/4)     // 192 float4 per row
#define RPB 8         // source rows per scatter work item
#define NROWS (BB*TT) // 36928
#define NSCAT (NROWS/RPB) // 4616
#define NITEMS (BB + NSCAT)
#define NBLK 592      // 148 SMs * 4 blocks — must all be co-resident
#define NTHR 192
#define NWARPS (NBLK*(NTHR/32)) // 3552
#define NPAIRS (NROWS/2)        // 18464

// Scratch (no device allocation allowed)
__device__ float g_logits[NROWS];
__device__ int   g_rank[NROWS];
__device__ int   g_skip[BB*NSKIP];
__device__ float g_weights[BB*NSKIP];
__device__ int   g_bar1 = 0, g_bar2 = 0;   // monotonic, replay-safe

// Grid-wide barrier: monotonic counter, works across graph replays.
__device__ __forceinline__ void grid_barrier(int* ctr) {
    __syncthreads();
    if (threadIdx.x == 0) {
        __threadfence();                      // release prior writes (cumulative)
        int old = atomicAdd(ctr, 1);
        int target = old - (old % NBLK) + NBLK;
        while (atomicAdd(ctr, 0) < target) { }
        __threadfence();                      // acquire
    }
    __syncthreads();
}

__global__ void __launch_bounds__(NTHR, 4)
fused_gate_kernel(const float* __restrict__ x,
                  const float* __restrict__ w,
                  const float* __restrict__ bias,
                  float* __restrict__ out) {
    __shared__ float s[TT];
    __shared__ float skipP[NSKIP];
    __shared__ float skipE[NSKIP];

    const float4* xin = reinterpret_cast<const float4*>(x);
    const float4* w4  = reinterpret_cast<const float4*>(w);
    float4* o4 = reinterpret_cast<float4*>(out);

    int tid  = threadIdx.x;
    int lane = tid & 31;
    int gwarp = blockIdx.x * (NTHR/32) + (tid >> 5);

    // ================= Phase 1: logits (2 rows per warp, strided sweep) =================
    {
        float4 wv[6];
        #pragma unroll
        for (int k = 0; k < 6; k++) wv[k] = __ldg(&w4[k*32 + lane]);
        float bv = __ldg(bias);

        for (int pair = gwarp; pair < NPAIRS; pair += NWARPS) {
            int row0 = pair * 2;
            const float4* xr0 = xin + (size_t)row0 * D4;
            const float4* xr1 = xr0 + D4;

            float4 a0[6], a1[6];
            #pragma unroll
            for (int k = 0; k < 6; k++) a0[k] = xr0[k*32 + lane];
            #pragma unroll
            for (int k = 0; k < 6; k++) a1[k] = xr1[k*32 + lane];

            float acc0 = 0.f, acc1 = 0.f;
            #pragma unroll
            for (int k = 0; k < 6; k++) {
                acc0 = fmaf(a0[k].x, wv[k].x, acc0);
                acc0 = fmaf(a0[k].y, wv[k].y, acc0);
                acc0 = fmaf(a0[k].z, wv[k].z, acc0);
                acc0 = fmaf(a0[k].w, wv[k].w, acc0);
                acc1 = fmaf(a1[k].x, wv[k].x, acc1);
                acc1 = fmaf(a1[k].y, wv[k].y, acc1);
                acc1 = fmaf(a1[k].z, wv[k].z, acc1);
                acc1 = fmaf(a1[k].w, wv[k].w, acc1);
            }
            #pragma unroll
            for (int off = 16; off; off >>= 1) {
                acc0 += __shfl_xor_sync(0xffffffffu, acc0, off);
                acc1 += __shfl_xor_sync(0xffffffffu, acc1, off);
            }
            if (lane == 0) {
                g_logits[row0]     = acc0 + bv;
                g_logits[row0 + 1] = acc1 + bv;
            }
        }
    }

    grid_barrier(&g_bar1);

    // ================= Phase 2: rank + skip softmax (blocks 0..63) =================
    if (blockIdx.x < BB) {
        int b = blockIdx.x;
        for (int i = tid; i < TT; i += NTHR) s[i] = g_logits[b*TT + i];
        __syncthreads();

        for (int i = tid; i < TT; i += NTHR) {
            float my = s[i];
            int rank = 0;
            #pragma unroll 8
            for (int j = 0; j < TT; j++) {
                float v = s[j];
                rank += (v > my) || (v == my && j < i);   // stable: lower index wins
            }
            g_rank[b*TT + i] = rank;
            if (rank >= DENS) {
                int pos = (TT - 1) - rank;                // ascending skipped order
                g_skip[b*NSKIP + pos] = i;
                skipP[pos] = 1.f / (1.f + expf(-my));     // sigmoid prob
            }
        }
        __syncthreads();

        if (tid < NSKIP) {
            float m = -1e30f;
            #pragma unroll
            for (int j = 0; j < NSKIP; j++) m = fmaxf(m, skipP[j]);
            skipE[tid] = expf(skipP[tid] - m);
        }
        __syncthreads();

        if (tid < NSKIP) {
            float sum = 0.f;
            #pragma unroll
            for (int j = 0; j < NSKIP; j++) sum += skipE[j];
            g_weights[b*NSKIP + tid] = skipE[tid] / sum;
        }
    }

    grid_barrier(&g_bar2);

    // ================= Phase 3: scatter (reversed) + summaries =================
    {
        const size_t skipBase = (size_t)BB * DENS * D4;
        const size_t sumBase  = (size_t)BB * (DENS + NSKIP) * D4;

        for (int it = blockIdx.x; it < NITEMS; it += NBLK) {
            if (it < BB) {
                // ---- summary for batch `it` (first iteration, hidden under scatter) ----
                int b = it;
                __syncthreads();
                if (tid < NSKIP) {
                    skipP[tid] = g_weights[b*NSKIP + tid];        // reuse smem: weights
                    s[tid] = __int_as_float(g_skip[b*NSKIP + tid]); // reuse smem: indices
                }
                __syncthreads();

                float4 acc = make_float4(0.f, 0.f, 0.f, 0.f);
                #pragma unroll 2
                for (int sI = 0; sI < NSKIP; sI++) {
                    int src = __float_as_int(s[sI]);
                    float wgt = skipP[sI];
                    float4 vv = xin[((size_t)b*TT + src) * D4 + tid];
                    acc.x = fmaf(wgt, vv.x, acc.x);
                    acc.y = fmaf(wgt, vv.y, acc.y);
                    acc.z = fmaf(wgt, vv.z, acc.z);
                    acc.w = fmaf(wgt, vv.w, acc.w);
                }
                o4[sumBase + (size_t)b * D4 + tid] = acc;
            } else {
                // ---- scatter of RPB rows, reversed traversal (freshest L2 lines first) ----
                int sb = (NSCAT - 1) - (it - BB);
                int base = sb * RPB;

                float4 v[RPB];
                #pragma unroll
                for (int r = 0; r < RPB; r++)
                    v[r] = __ldcs(&xin[((size_t)(base + r)) * D4 + tid]);

                #pragma unroll
                for (int r = 0; r < RPB; r++) {
                    int src = base + r;
                    int b = src / TT;
                    int rank = g_rank[src];
                    size_t off = (rank < DENS)
                        ? ((size_t)(b*DENS + rank) * D4)
                        : (skipBase + (size_t)(b*NSKIP + ((TT-1) - rank)) * D4);
                    __stcs(&o4[off + tid], v[r]);
                }
            }
        }
    }
}

extern "C" void kernel_launch(void* const* d_in, const int* in_sizes, int n_in,
                              void* d_out, int out_size) {
    const float* x    = (const float*)d_in[0];
    const float* w    = (const float*)d_in[1];
    const float* bias = (const float*)d_in[2];
    float* out = (float*)d_out;

    fused_gate_kernel<<<NBLK, NTHR>>>(x, w, bias, out);
}